// round 7
// baseline (speedup 1.0000x reference)
#include <cuda_runtime.h>

// ---------------------------------------------------------------------------
// SpatialFrequencyLoss: sum_i w_i * mean( (LoG_i * (input - target))^2 )
// LoG kernel is rank-3 separable:  a = f (x) u  +  u (x) f  -  c * ones
// rowT pass: along x; writes TRANSPOSED planes FH_T[x][y]=(aH,aF), A1_T[x][y]
// colT pass: along y on transposed planes (contiguous!), SMEM-staged lines,
//            d = f*aH + h*aF - c*Box ; accumulate d^2. No inner-loop LDG.
// 3 concurrent stream chains (graph fork/join), 3 private plane sets.
// Reflect padding (numpy 'reflect') applied at staging time only.
// ---------------------------------------------------------------------------

namespace {
constexpr int Hh = 512, Ww = 512, NCc = 4 * 3;
constexpr int NPIX = NCc * Hh * Ww;  // 3,145,728
}

__device__ float  g_diff[NPIX];
__device__ unsigned long long g_FHT[3][NPIX];  // transposed (aH,aF) pairs
__device__ float  g_A1T[3][NPIX];              // transposed box_x plane
__device__ double g_acc[6];

// ---------------- f32x2 packed helpers --------------------------------------

__device__ __forceinline__ unsigned long long pk2(float lo, float hi) {
    unsigned long long r;
    asm("mov.b64 %0, {%1, %2};" : "=l"(r) : "f"(lo), "f"(hi));
    return r;
}
__device__ __forceinline__ unsigned long long ffma2(unsigned long long a,
                                                    unsigned long long b,
                                                    unsigned long long c) {
    unsigned long long d;
    asm("fma.rn.f32x2 %0, %1, %2, %3;" : "=l"(d) : "l"(a), "l"(b), "l"(c));
    return d;
}
__device__ __forceinline__ unsigned long long add2(unsigned long long a,
                                                   unsigned long long b) {
    unsigned long long d;
    asm("add.rn.f32x2 %0, %1, %2;" : "=l"(d) : "l"(a), "l"(b));
    return d;
}
__device__ __forceinline__ float2 upk(unsigned long long a) {
    float2 v;
    asm("mov.b64 {%0, %1}, %2;" : "=f"(v.x), "=f"(v.y) : "l"(a));
    return v;
}

// ---------------- compile-time taps ----------------------------------------

__host__ __device__ constexpr double cexp(double x) {
    double r = x; int n = 0;
    while (r < -0.5) { r += 1.0; ++n; }
    double term = 1.0, sum = 1.0;
    for (int i = 1; i < 30; ++i) { term *= r / (double)i; sum += term; }
    for (int i = 0; i < n; ++i) sum /= 2.71828182845904523536028747135266;
    return sum;
}

template<int K> struct TapsT { float f[K]; float h[K]; float c; };

template<int K>
__host__ __device__ constexpr TapsT<K> make_taps(double sigma) {
    TapsT<K> T{};
    const double ss = sigma * sigma;
    const double norm = 1.0 / (2.0 * 3.14159265358979323846 * ss * ss);
    double Sf = 0.0, Sh = 0.0;
    for (int i = 0; i < K; ++i) {
        const double x = (double)(i - (K - 1) / 2);
        const double u = cexp(-(x * x) / (2.0 * ss));
        const double fv = (x * x - ss) * u * norm;
        T.f[i] = (float)fv;
        T.h[i] = (float)u;
        Sf += fv; Sh += u;
    }
    T.c = (float)(2.0 * Sf * Sh / ((double)K * (double)K));
    return T;
}

template<int SI> struct Cfg;
template<> struct Cfg<0> { static constexpr int K = 5;   static constexpr double S = 0.6;  };
template<> struct Cfg<1> { static constexpr int K = 11;  static constexpr double S = 1.2;  };
template<> struct Cfg<2> { static constexpr int K = 21;  static constexpr double S = 2.4;  };
template<> struct Cfg<3> { static constexpr int K = 39;  static constexpr double S = 4.8;  };
template<> struct Cfg<4> { static constexpr int K = 77;  static constexpr double S = 9.6;  };
template<> struct Cfg<5> { static constexpr int K = 155; static constexpr double S = 19.2; };

__device__ __forceinline__ int refl(int i, int n) {
    if (i < 0) i = -i;
    if (i >= n) i = 2 * n - 2 - i;
    return i;
}
__device__ __forceinline__ constexpr int skew(int c) { return c + (c >> 3); }

// ---------------- diff ------------------------------------------------------

__global__ void diff_k(const float4* __restrict__ a, const float4* __restrict__ b) {
    if (blockIdx.x == 0 && threadIdx.x < 6) g_acc[threadIdx.x] = 0.0;
    int i = blockIdx.x * blockDim.x + threadIdx.x;
    if (i < NPIX / 4) {
        float4 x = a[i], y = b[i];
        float4 d;
        d.x = x.x - y.x; d.y = x.y - y.y; d.z = x.z - y.z; d.w = x.w - y.w;
        reinterpret_cast<float4*>(g_diff)[i] = d;
    }
}

// ---------------- rowT pass --------------------------------------------------
// Block: 8 image rows x 512 cols; 512 threads, one x-column each (8 y outputs).
// Stage: interleaved stage[j*10 + r] (pitch 10 -> min-phase LDS.64).
// Output transposed via skewed SMEM bounce -> coalesced 64B/32B global runs.

template<int SI>
__global__ void __launch_bounds__(512) rowT_k(int ps) {
    constexpr int K = Cfg<SI>::K;
    constexpr TapsT<K> T = make_taps<K>(Cfg<SI>::S);
    constexpr int P  = K / 2;
    constexpr int PW = Ww + 2 * P;
    constexpr int STAGE_BYTES  = PW * 10 * 4;
    constexpr int BFH_BYTES    = 512 * 9 * 8;            // bounce FH (pitch 9 u64)
    constexpr int BA1_BYTES    = 512 * 9 * 4;            // bounce A1 (pitch 9 f32)
    constexpr int SMEM_BYTES   = (STAGE_BYTES > BFH_BYTES + BA1_BYTES)
                                   ? STAGE_BYTES : (BFH_BYTES + BA1_BYTES);

    __shared__ alignas(16) char smem[SMEM_BYTES];
    float* __restrict__ stage = reinterpret_cast<float*>(smem);

    const int tid = threadIdx.x;
    const int img = blockIdx.y;
    const int y0  = blockIdx.x * 8;
    const float* __restrict__ src = g_diff + img * (Hh * Ww);

    for (int idx = tid; idx < 8 * PW; idx += 512) {
        const int r = idx / PW, j = idx - r * PW;
        stage[j * 10 + r] = src[(y0 + r) * Ww + refl(j - P, Ww)];
    }
    __syncthreads();

    const int x = tid;
    unsigned long long aF2[4], aH2[4], aB2[4];
#pragma unroll
    for (int p = 0; p < 4; ++p) { aF2[p] = 0ull; aH2[p] = 0ull; aB2[p] = 0ull; }

#pragma unroll
    for (int t = 0; t < K; ++t) {
        const float* b = stage + (x + t) * 10;
        unsigned long long d0 = *reinterpret_cast<const unsigned long long*>(b + 0);
        unsigned long long d1 = *reinterpret_cast<const unsigned long long*>(b + 2);
        unsigned long long d2 = *reinterpret_cast<const unsigned long long*>(b + 4);
        unsigned long long d3 = *reinterpret_cast<const unsigned long long*>(b + 6);
        const unsigned long long tf = pk2(T.f[t], T.f[t]);
        const unsigned long long th = pk2(T.h[t], T.h[t]);
        aF2[0] = ffma2(tf, d0, aF2[0]); aH2[0] = ffma2(th, d0, aH2[0]); aB2[0] = add2(aB2[0], d0);
        aF2[1] = ffma2(tf, d1, aF2[1]); aH2[1] = ffma2(th, d1, aH2[1]); aB2[1] = add2(aB2[1], d1);
        aF2[2] = ffma2(tf, d2, aF2[2]); aH2[2] = ffma2(th, d2, aH2[2]); aB2[2] = add2(aB2[2], d2);
        aF2[3] = ffma2(tf, d3, aF2[3]); aH2[3] = ffma2(th, d3, aH2[3]); aB2[3] = add2(aB2[3], d3);
    }
    __syncthreads();   // staging no longer needed; reuse as bounce

    unsigned long long* __restrict__ bFH = reinterpret_cast<unsigned long long*>(smem);
    float* __restrict__ bA1 = reinterpret_cast<float*>(smem + BFH_BYTES);
#pragma unroll
    for (int p = 0; p < 4; ++p) {
        const float2 f2 = upk(aF2[p]);
        const float2 h2 = upk(aH2[p]);
        const float2 b2 = upk(aB2[p]);
        bFH[x * 9 + 2 * p]     = pk2(h2.x, f2.x);   // lo = aH, hi = aF
        bFH[x * 9 + 2 * p + 1] = pk2(h2.y, f2.y);
        bA1[x * 9 + 2 * p]     = b2.x;
        bA1[x * 9 + 2 * p + 1] = b2.y;
    }
    __syncthreads();

    unsigned long long* __restrict__ FHT = g_FHT[ps] + img * (Hh * Ww);
    float* __restrict__ A1T = g_A1T[ps] + img * (Hh * Ww);
#pragma unroll
    for (int it = 0; it < 8; ++it) {
        const int idx = tid + it * 512;
        const int xx = idx >> 3, yy = idx & 7;
        FHT[xx * Hh + y0 + yy] = bFH[xx * 9 + yy];
        A1T[xx * Hh + y0 + yy] = bA1[xx * 9 + yy];
    }
}

// ---------------- colT pass --------------------------------------------------
// Block: 4 x-columns; stages full padded column lines (contiguous reads) into
// skewed SMEM; 64 threads/column x 8 y-outputs; register u64 ring; no LDG in
// the tap loop. Accumulates squared loss -> block reduce -> atomic.

template<int SI>
__global__ void __launch_bounds__(256) colT_k(int ps) {
    constexpr int K = Cfg<SI>::K;
    constexpr TapsT<K> T = make_taps<K>(Cfg<SI>::S);
    constexpr int P  = K / 2;
    constexpr int PW = Hh + 2 * P;
    constexpr int LP = PW + (PW >> 3) + 2;   // skewed line pitch

    __shared__ alignas(16) unsigned long long sFH[4 * LP];
    __shared__ float sA1[4 * LP];

    const int tid = threadIdx.x;
    const int img = blockIdx.y;
    const int x0  = blockIdx.x * 4;
    const unsigned long long* __restrict__ FHT = g_FHT[ps] + img * (Hh * Ww);
    const float* __restrict__ A1T = g_A1T[ps] + img * (Hh * Ww);

    for (int idx = tid; idx < 4 * PW; idx += 256) {
        const int line = idx / PW, j = idx - line * PW;
        const int y = refl(j - P, Hh);
        const int m = line * LP + skew(j);
        sFH[m] = FHT[(x0 + line) * Hh + y];
        sA1[m] = A1T[(x0 + line) * Hh + y];
    }
    __syncthreads();

    const int sub   = tid >> 6;
    const int ylane = tid & 63;
    const unsigned long long* __restrict__ lFH = sFH + sub * LP + 9 * ylane;
    const float* __restrict__ lA1 = sA1 + sub * LP + 9 * ylane;

    unsigned long long w[8], acc[8];
#pragma unroll
    for (int o = 0; o < 8; ++o) { w[o] = lFH[skew(o)]; acc[o] = 0ull; }
    float S = 0.f;

#pragma unroll
    for (int t = 0; t < K; ++t) {
        if (t > 0) w[(t + 7) & 7] = lFH[skew(t + 7)];
        const unsigned long long tp = pk2(T.f[t], T.h[t]);
        S += lA1[skew(t)];
#pragma unroll
        for (int o = 0; o < 8; ++o)
            acc[o] = ffma2(tp, w[(t + o) & 7], acc[o]);
    }

    float box = S, local = 0.f;
#pragma unroll
    for (int o = 0; o < 8; ++o) {
        if (o) box += lA1[skew(K - 1 + o)] - lA1[skew(o - 1)];
        const float2 p = upk(acc[o]);
        const float v = fmaf(-T.c, box, p.x + p.y);
        local = fmaf(v, v, local);
    }

#pragma unroll
    for (int off = 16; off; off >>= 1)
        local += __shfl_xor_sync(0xffffffffu, local, off);
    __shared__ float ws[8];
    if ((tid & 31) == 0) ws[tid >> 5] = local;
    __syncthreads();
    if (tid == 0) {
        double tot = 0.0;
#pragma unroll
        for (int i = 0; i < 8; ++i) tot += (double)ws[i];
        atomicAdd(&g_acc[SI], tot);
    }
}

// ---------------- final -----------------------------------------------------

__global__ void final_k(float* __restrict__ out) {
    const double w[6] = {600.0, 500.0, 400.0, 20.0, 10.0, 10.0};
    double l = 0.0;
    for (int i = 0; i < 6; ++i) l += w[i] * g_acc[i];
    out[0] = (float)(l / (double)NPIX);
}

// ---------------- launcher ---------------------------------------------------

template<int SI> static void run_sigma(cudaStream_t st, int ps) {
    rowT_k<SI><<<dim3(Hh / 8, NCc), 512, 0, st>>>(ps);
    colT_k<SI><<<dim3(Ww / 4, NCc), 256, 0, st>>>(ps);
}

extern "C" void kernel_launch(void* const* d_in, const int* in_sizes, int n_in,
                              void* d_out, int out_size) {
    (void)in_sizes; (void)n_in; (void)out_size;
    const float4* a = (const float4*)d_in[0];
    const float4* b = (const float4*)d_in[1];

    static cudaStream_t sA = nullptr, sB = nullptr, sC = nullptr;
    static cudaEvent_t eD = nullptr, eA = nullptr, eB = nullptr, eC = nullptr;
    if (!sA) {
        cudaStreamCreateWithFlags(&sA, cudaStreamNonBlocking);
        cudaStreamCreateWithFlags(&sB, cudaStreamNonBlocking);
        cudaStreamCreateWithFlags(&sC, cudaStreamNonBlocking);
        cudaEventCreateWithFlags(&eD, cudaEventDisableTiming);
        cudaEventCreateWithFlags(&eA, cudaEventDisableTiming);
        cudaEventCreateWithFlags(&eB, cudaEventDisableTiming);
        cudaEventCreateWithFlags(&eC, cudaEventDisableTiming);
    }

    diff_k<<<(NPIX / 4 + 511) / 512, 512>>>(a, b);   // legacy stream
    cudaEventRecord(eD, 0);
    cudaStreamWaitEvent(sA, eD, 0);
    cudaStreamWaitEvent(sB, eD, 0);
    cudaStreamWaitEvent(sC, eD, 0);

    run_sigma<5>(sA, 0);  run_sigma<0>(sA, 0);   // chain A
    run_sigma<4>(sB, 1);  run_sigma<2>(sB, 1);   // chain B
    run_sigma<3>(sC, 2);  run_sigma<1>(sC, 2);   // chain C

    cudaEventRecord(eA, sA);
    cudaEventRecord(eB, sB);
    cudaEventRecord(eC, sC);
    cudaStreamWaitEvent(0, eA, 0);
    cudaStreamWaitEvent(0, eB, 0);
    cudaStreamWaitEvent(0, eC, 0);

    final_k<<<1, 1>>>((float*)d_out);                // legacy stream
}

// round 9
// speedup vs baseline: 2.6929x; 2.6929x over previous
#include <cuda_runtime.h>

// ---------------------------------------------------------------------------
// SpatialFrequencyLoss: sum_i w_i * mean( (LoG_i * (input - target))^2 )
// LoG kernel is rank-3 separable:  a = f (x) u  +  u (x) f  -  c * ones
// sigma0-2 (K=5,11,21): exact, full-res row+col passes (proven R6 kernels).
// sigma3-5 (K=39,77,155): computed on 2x box-downsampled diff with exact
//   block-averaged taps  F(v)=f(2v)+f(2v+1), U(v)=u(2v)+u(2v+1), c2=4m.
//   Padded D plane holds true reflected block averages -> no boundary approx.
//   Loss term = mean over even output sites (alias-free for these sigma).
// 3 concurrent stream chains (R6-proven graph topology); down_k on the
// legacy stream before the fork (keeps the graph narrow - teardown-safe).
// ---------------------------------------------------------------------------

namespace {
constexpr int Hh = 512, Ww = 512, NCc = 4 * 3;
constexpr int NPIX = NCc * Hh * Ww;      // 3,145,728
constexpr int W2 = 256, H2 = 256, GPAD = 40;
constexpr int DP = W2 + 2 * GPAD;        // 336 padded dim for D
constexpr int HPL = 336;                 // padded plane height (rows -GPAD..295)
}

__device__ float  g_diff[NPIX];
__device__ float4 g_FH[3][NPIX / 2];     // full-res (aH,aF) pairs, 2 px/float4
__device__ float4 g_A14[3][NPIX / 4];    // full-res A1 plane
__device__ float  g_Dh[NCc * DP * DP];   // padded downsampled diff
__device__ unsigned long long g_FHh[3][NCc * HPL * W2];  // half (aU,aF)
__device__ float  g_A1h[3][NCc * HPL * W2];              // half box plane
__device__ double g_acc[6];

// ---------------- f32x2 packed helpers --------------------------------------

__device__ __forceinline__ unsigned long long pk2(float lo, float hi) {
    unsigned long long r;
    asm("mov.b64 %0, {%1, %2};" : "=l"(r) : "f"(lo), "f"(hi));
    return r;
}
__device__ __forceinline__ unsigned long long ffma2(unsigned long long a,
                                                    unsigned long long b,
                                                    unsigned long long c) {
    unsigned long long d;
    asm("fma.rn.f32x2 %0, %1, %2, %3;" : "=l"(d) : "l"(a), "l"(b), "l"(c));
    return d;
}
__device__ __forceinline__ float2 upk(unsigned long long a) {
    float2 v;
    asm("mov.b64 {%0, %1}, %2;" : "=f"(v.x), "=f"(v.y) : "l"(a));
    return v;
}

// ---------------- compile-time taps ----------------------------------------

__host__ __device__ constexpr double cexp(double x) {
    double r = x; int n = 0;
    while (r < -0.5) { r += 1.0; ++n; }
    double term = 1.0, sum = 1.0;
    for (int i = 1; i < 30; ++i) { term *= r / (double)i; sum += term; }
    for (int i = 0; i < n; ++i) sum /= 2.71828182845904523536028747135266;
    return sum;
}

__host__ __device__ constexpr double u_at(int x, int P, double ss) {
    if (x < -P || x > P) return 0.0;
    return cexp(-((double)x * x) / (2.0 * ss));
}
__host__ __device__ constexpr double f_at(int x, int P, double ss, double norm) {
    if (x < -P || x > P) return 0.0;
    return ((double)x * x - ss) * cexp(-((double)x * x) / (2.0 * ss)) * norm;
}

template<int K> struct TapsT { float f[K]; float h[K]; float c; };

template<int K>
__host__ __device__ constexpr TapsT<K> make_taps(double sigma) {
    TapsT<K> T{};
    const double ss = sigma * sigma;
    const double norm = 1.0 / (2.0 * 3.14159265358979323846 * ss * ss);
    const int P = K / 2;
    double Sf = 0.0, Sh = 0.0;
    for (int i = 0; i < K; ++i) {
        const double fv = f_at(i - P, P, ss, norm);
        const double uv = u_at(i - P, P, ss);
        T.f[i] = (float)fv;
        T.h[i] = (float)uv;
        Sf += fv; Sh += uv;
    }
    T.c = (float)(2.0 * Sf * Sh / ((double)K * (double)K));
    return T;
}

// Half-res taps: F(v)=f(2v)+f(2v+1), U likewise; c2 = 4m = 8*Sf*Sh/K^2.
template<int K2> struct TapsH { float F[K2]; float U[K2]; float c; };

template<int K2>
__host__ __device__ constexpr TapsH<K2> make_tapsH(double sigma, int K, int PL) {
    TapsH<K2> T{};
    const double ss = sigma * sigma;
    const double norm = 1.0 / (2.0 * 3.14159265358979323846 * ss * ss);
    const int P = K / 2;
    for (int t = 0; t < K2; ++t) {
        const int v = t - PL;
        T.F[t] = (float)(f_at(2 * v, P, ss, norm) + f_at(2 * v + 1, P, ss, norm));
        T.U[t] = (float)(u_at(2 * v, P, ss) + u_at(2 * v + 1, P, ss));
    }
    double Sf = 0.0, Sh = 0.0;
    for (int x = -P; x <= P; ++x) { Sf += f_at(x, P, ss, norm); Sh += u_at(x, P, ss); }
    T.c = (float)(8.0 * Sf * Sh / ((double)K * (double)K));
    return T;
}

template<int SI> struct Cfg;
template<> struct Cfg<0> { static constexpr int K = 5;  static constexpr double S = 0.6; static constexpr int CR = 16; };
template<> struct Cfg<1> { static constexpr int K = 11; static constexpr double S = 1.2; static constexpr int CR = 16; };
template<> struct Cfg<2> { static constexpr int K = 21; static constexpr double S = 2.4; static constexpr int CR = 16; };

template<int SI> struct CH;
template<> struct CH<3> { static constexpr int K = 39;  static constexpr double S = 4.8;  static constexpr int K2 = 20; static constexpr int PL = 10; static constexpr int PR = 9;  };
template<> struct CH<4> { static constexpr int K = 77;  static constexpr double S = 9.6;  static constexpr int K2 = 39; static constexpr int PL = 19; static constexpr int PR = 19; };
template<> struct CH<5> { static constexpr int K = 155; static constexpr double S = 19.2; static constexpr int K2 = 78; static constexpr int PL = 39; static constexpr int PR = 38; };

__device__ __forceinline__ int refl(int i, int n) {
    if (i < 0) i = -i;
    if (i >= n) i = 2 * n - 2 - i;
    return i;
}

// ---------------- diff ------------------------------------------------------

__global__ void diff_k(const float4* __restrict__ a, const float4* __restrict__ b) {
    if (blockIdx.x == 0 && threadIdx.x < 6) g_acc[threadIdx.x] = 0.0;
    int i = blockIdx.x * blockDim.x + threadIdx.x;
    if (i < NPIX / 4) {
        float4 x = a[i], y = b[i];
        float4 d;
        d.x = x.x - y.x; d.y = x.y - y.y; d.z = x.z - y.z; d.w = x.w - y.w;
        reinterpret_cast<float4*>(g_diff)[i] = d;
    }
}

// ---------------- downsample (padded, true reflected block averages) --------

__global__ void down_k() {
    const int img = blockIdx.y;
    const int yy  = blockIdx.x;            // 0..DP-1
    const int wy  = yy - GPAD;
    const float* __restrict__ src = g_diff + img * (Hh * Ww);
    const int r0 = refl(2 * wy, Hh), r1 = refl(2 * wy + 1, Hh);
    float* __restrict__ dst = g_Dh + (img * DP + yy) * DP;
    for (int xx = threadIdx.x; xx < DP; xx += blockDim.x) {
        const int wx = xx - GPAD;
        const int c0 = refl(2 * wx, Ww), c1 = refl(2 * wx + 1, Ww);
        dst[xx] = 0.25f * (src[r0 * Ww + c0] + src[r0 * Ww + c1] +
                           src[r1 * Ww + c0] + src[r1 * Ww + c1]);
    }
}

// ---------------- full-res row pass (R6, proven) ----------------------------

template<int SI>
__global__ void __launch_bounds__(128) row_k(int ps) {
    constexpr int K = Cfg<SI>::K;
    constexpr TapsT<K> T = make_taps<K>(Cfg<SI>::S);
    constexpr int P = K / 2;
    constexpr int PW = Ww + 2 * P;
    constexpr int PWpad = (PW + 3) & ~3;

    __shared__ alignas(16) float s[2 * PWpad];
    const int tid  = threadIdx.x;
    const int row0 = blockIdx.x * 2;
#pragma unroll
    for (int rr = 0; rr < 2; ++rr) {
        const float* __restrict__ src = g_diff + (row0 + rr) * Ww;
        for (int i = tid; i < PW; i += 128) s[rr * PWpad + i] = src[refl(i - P, Ww)];
    }
    __syncthreads();

    const int sub = tid >> 6;
    const int x0  = (tid & 63) * 8;
    const float* __restrict__ sr = s + sub * PWpad + x0;

    float w[12];
#pragma unroll
    for (int i = 0; i < 8; i += 4) {
        const float4 v = *reinterpret_cast<const float4*>(sr + i);
        w[i] = v.x; w[i + 1] = v.y; w[i + 2] = v.z; w[i + 3] = v.w;
    }

    unsigned long long aFH[8];
#pragma unroll
    for (int o = 0; o < 8; ++o) aFH[o] = 0ull;
    float S = 0.f;

    constexpr int G = K / 4, REM = K % 4;
#pragma unroll
    for (int tg = 0; tg < G; ++tg) {
        const float4 v = *reinterpret_cast<const float4*>(sr + 8 + 4 * tg);
        w[8] = v.x; w[9] = v.y; w[10] = v.z; w[11] = v.w;
#pragma unroll
        for (int j = 0; j < 4; ++j) {
            const int t = 4 * tg + j;
            const unsigned long long tp = pk2(T.f[t], T.h[t]);
            S += w[j];
#pragma unroll
            for (int o = 0; o < 8; ++o) {
                const unsigned long long dd = pk2(w[j + o], w[j + o]);
                aFH[o] = ffma2(tp, dd, aFH[o]);
            }
        }
#pragma unroll
        for (int i = 0; i < 8; ++i) w[i] = w[i + 4];
    }
    if (REM >= 2) w[8] = sr[4 * G + 8];
    if (REM == 3) w[9] = sr[4 * G + 9];
#pragma unroll
    for (int j = 0; j < REM; ++j) {
        const int t = 4 * G + j;
        const unsigned long long tp = pk2(T.f[t], T.h[t]);
        S += w[j];
#pragma unroll
        for (int o = 0; o < 8; ++o) {
            const unsigned long long dd = pk2(w[j + o], w[j + o]);
            aFH[o] = ffma2(tp, dd, aFH[o]);
        }
    }

    float box[8];
    box[0] = S;
#pragma unroll
    for (int o = 1; o < 8; ++o)
        box[o] = box[o - 1] - sr[o - 1] + sr[o + K - 1];

    const int base = (row0 + sub) * Ww + x0;
    float4* __restrict__ fh = g_FH[ps] + base / 2;
#pragma unroll
    for (int o = 0; o < 8; o += 2) {
        const float2 p0 = upk(aFH[o]);      // x = aF, y = aH
        const float2 p1 = upk(aFH[o + 1]);
        fh[o / 2] = make_float4(p0.y, p0.x, p1.y, p1.x);   // store (aH, aF)
    }
    float4* __restrict__ a1 = g_A14[ps] + base / 4;
    a1[0] = make_float4(box[0], box[1], box[2], box[3]);
    a1[1] = make_float4(box[4], box[5], box[6], box[7]);
}

// ---------------- full-res col pass (R6, proven) ----------------------------

template<int SI, bool FAST>
__device__ __forceinline__ float col_body(int ps, int pb, int y0) {
    constexpr int K = Cfg<SI>::K;
    constexpr TapsT<K> T = make_taps<K>(Cfg<SI>::S);
    constexpr int P = K / 2;
    constexpr int R = Cfg<SI>::CR;
    constexpr int PF = 6;
    constexpr int PI = (PF < K) ? PF : K;

    const unsigned long long* __restrict__ FH = (const unsigned long long*)g_FH[ps];
    const float* __restrict__ A1 = (const float*)g_A14[ps];
    const int yb = y0 - P;

    auto ridx = [&](int j) -> int {
        return pb + (FAST ? (yb + j) : refl(yb + j, Hh)) * Ww;
    };

    unsigned long long ring[R], acc[R];
#pragma unroll
    for (int o = 0; o < R; ++o) acc[o] = 0ull;

#pragma unroll
    for (int j = 0; j < R - 1; ++j) ring[j] = FH[ridx(j)];
    unsigned long long pend[PF];
#pragma unroll
    for (int q = 0; q < PI; ++q) pend[q] = FH[ridx(R - 1 + q)];

#pragma unroll
    for (int t = 0; t < K; ++t) {
        const unsigned long long v = pend[t % PF];
        if (t + PF < K) pend[t % PF] = FH[ridx(R - 1 + t + PF)];
        const int sl = (t + R - 1) & (R - 1);
        ring[sl] = v;
        const unsigned long long tp = pk2(T.f[t], T.h[t]);
#pragma unroll
        for (int o = 0; o < R; ++o)
            acc[o] = ffma2(tp, ring[(t + o) & (R - 1)], acc[o]);
    }

    float S = 0.f;
#pragma unroll
    for (int j = 0; j < K; ++j) S += A1[ridx(j)];

    float box = S, local = 0.f;
#pragma unroll
    for (int o = 0; o < R; ++o) {
        if (o) box += A1[ridx(K - 1 + o)] - A1[ridx(o - 1)];
        const float2 p = upk(acc[o]);
        const float v = fmaf(-T.c, box, p.x + p.y);
        local = fmaf(v, v, local);
    }
    return local;
}

template<int SI>
__global__ void __launch_bounds__(128) col_k(int ps) {
    constexpr int K = Cfg<SI>::K;
    constexpr int P = K / 2;
    constexpr int R = Cfg<SI>::CR;

    const int x  = blockIdx.x * 128 + threadIdx.x;
    const int y0 = blockIdx.y * R;
    const int pb = blockIdx.z * (Hh * Ww) + x;

    const int yb = y0 - P;
    const bool interior = (yb >= 0) && (yb + K + R - 2 < Hh);
    float local = interior ? col_body<SI, true>(ps, pb, y0)
                           : col_body<SI, false>(ps, pb, y0);

#pragma unroll
    for (int off = 16; off; off >>= 1)
        local += __shfl_xor_sync(0xffffffffu, local, off);
    __shared__ float ws[4];
    if ((threadIdx.x & 31) == 0) ws[threadIdx.x >> 5] = local;
    __syncthreads();
    if (threadIdx.x == 0) {
        const double tot = (double)ws[0] + (double)ws[1] + (double)ws[2] + (double)ws[3];
        atomicAdd(&g_acc[SI], tot);
    }
}

// ---------------- half-res row pass -----------------------------------------
// Processes padded rows yy in [0, HPL); 128 thr = 4 rows x 32 lanes x 8 outs.

template<int SI>
__global__ void __launch_bounds__(128) rowh_k(int ps) {
    constexpr int K2 = CH<SI>::K2, PL = CH<SI>::PL, PR = CH<SI>::PR;
    constexpr TapsH<K2> T = make_tapsH<K2>(CH<SI>::S, CH<SI>::K, PL);
    constexpr int PW = W2 + PL + PR;
    constexpr int PWpad = (PW + 3) & ~3;

    __shared__ alignas(16) float s[4 * PWpad];
    const int tid = threadIdx.x;
    const int img = blockIdx.y;
    const int yy0 = blockIdx.x * 4;
    const float* __restrict__ src = g_Dh + (img * DP + yy0) * DP + (GPAD - PL);

    for (int idx = tid; idx < 4 * PW; idx += 128) {
        const int rr = idx / PW, j = idx - rr * PW;
        s[rr * PWpad + j] = src[rr * DP + j];
    }
    __syncthreads();

    const int sub = tid >> 5;
    const int x0  = (tid & 31) * 8;
    const float* __restrict__ sr = s + sub * PWpad + x0;

    float w[12];
#pragma unroll
    for (int i = 0; i < 8; i += 4) {
        const float4 v = *reinterpret_cast<const float4*>(sr + i);
        w[i] = v.x; w[i + 1] = v.y; w[i + 2] = v.z; w[i + 3] = v.w;
    }

    unsigned long long aFH[8];
#pragma unroll
    for (int o = 0; o < 8; ++o) aFH[o] = 0ull;
    float S = 0.f;

    constexpr int G = K2 / 4, REM = K2 % 4;
#pragma unroll
    for (int tg = 0; tg < G; ++tg) {
        const float4 v = *reinterpret_cast<const float4*>(sr + 8 + 4 * tg);
        w[8] = v.x; w[9] = v.y; w[10] = v.z; w[11] = v.w;
#pragma unroll
        for (int j = 0; j < 4; ++j) {
            const int t = 4 * tg + j;
            const unsigned long long tp = pk2(T.F[t], T.U[t]);
            S += w[j];
#pragma unroll
            for (int o = 0; o < 8; ++o) {
                const unsigned long long dd = pk2(w[j + o], w[j + o]);
                aFH[o] = ffma2(tp, dd, aFH[o]);
            }
        }
#pragma unroll
        for (int i = 0; i < 8; ++i) w[i] = w[i + 4];
    }
    if (REM >= 2) w[8] = sr[4 * G + 8];
    if (REM == 3) w[9] = sr[4 * G + 9];
#pragma unroll
    for (int j = 0; j < REM; ++j) {
        const int t = 4 * G + j;
        const unsigned long long tp = pk2(T.F[t], T.U[t]);
        S += w[j];
#pragma unroll
        for (int o = 0; o < 8; ++o) {
            const unsigned long long dd = pk2(w[j + o], w[j + o]);
            aFH[o] = ffma2(tp, dd, aFH[o]);
        }
    }

    float box[8];
    box[0] = S;
#pragma unroll
    for (int o = 1; o < 8; ++o)
        box[o] = box[o - 1] - sr[o - 1] + sr[o + K2 - 1];

    const int base = (img * HPL + yy0 + sub) * W2 + x0;
    unsigned long long* __restrict__ fh = g_FHh[ps] + base;
#pragma unroll
    for (int o = 0; o < 8; ++o) {
        const float2 p = upk(aFH[o]);          // x = aF, y = aU
        fh[o] = pk2(p.y, p.x);                 // store (aU, aF)
    }
    float* __restrict__ a1 = g_A1h[ps] + base;
    *reinterpret_cast<float4*>(a1)     = make_float4(box[0], box[1], box[2], box[3]);
    *reinterpret_cast<float4*>(a1 + 4) = make_float4(box[4], box[5], box[6], box[7]);
}

// ---------------- half-res col pass (no reflection: planes padded) ----------

template<int SI>
__global__ void __launch_bounds__(128) colh_k(int ps) {
    constexpr int K2 = CH<SI>::K2, PL = CH<SI>::PL;
    constexpr TapsH<K2> T = make_tapsH<K2>(CH<SI>::S, CH<SI>::K, PL);
    constexpr int R = 16;
    constexpr int PF = 6;
    constexpr int PI = (PF < K2) ? PF : K2;

    const int x   = blockIdx.x * 128 + threadIdx.x;
    const int y0  = blockIdx.y * R;
    const int img = blockIdx.z;
    const unsigned long long* __restrict__ FH = g_FHh[ps];
    const float* __restrict__ A1 = g_A1h[ps];
    const int pb = img * (HPL * W2) + x + (y0 - PL + GPAD) * W2;

    auto ridx = [&](int j) -> int { return pb + j * W2; };

    unsigned long long ring[R], acc[R];
#pragma unroll
    for (int o = 0; o < R; ++o) acc[o] = 0ull;

#pragma unroll
    for (int j = 0; j < R - 1; ++j) ring[j] = FH[ridx(j)];
    unsigned long long pend[PF];
#pragma unroll
    for (int q = 0; q < PI; ++q) pend[q] = FH[ridx(R - 1 + q)];

#pragma unroll
    for (int t = 0; t < K2; ++t) {
        const unsigned long long v = pend[t % PF];
        if (t + PF < K2) pend[t % PF] = FH[ridx(R - 1 + t + PF)];
        const int sl = (t + R - 1) & (R - 1);
        ring[sl] = v;
        const unsigned long long tp = pk2(T.F[t], T.U[t]);
#pragma unroll
        for (int o = 0; o < R; ++o)
            acc[o] = ffma2(tp, ring[(t + o) & (R - 1)], acc[o]);
    }

    float S = 0.f;
#pragma unroll
    for (int j = 0; j < K2; ++j) S += A1[ridx(j)];

    float box = S, local = 0.f;
#pragma unroll
    for (int o = 0; o < R; ++o) {
        if (o) box += A1[ridx(K2 - 1 + o)] - A1[ridx(o - 1)];
        const float2 p = upk(acc[o]);
        const float v = fmaf(-T.c, box, p.x + p.y);
        local = fmaf(v, v, local);
    }

#pragma unroll
    for (int off = 16; off; off >>= 1)
        local += __shfl_xor_sync(0xffffffffu, local, off);
    __shared__ float ws[4];
    if ((threadIdx.x & 31) == 0) ws[threadIdx.x >> 5] = local;
    __syncthreads();
    if (threadIdx.x == 0) {
        const double tot = (double)ws[0] + (double)ws[1] + (double)ws[2] + (double)ws[3];
        atomicAdd(&g_acc[SI], tot);
    }
}

// ---------------- final -----------------------------------------------------

__global__ void final_k(float* __restrict__ out) {
    const double w[6] = {600.0, 500.0, 400.0, 20.0, 10.0, 10.0};
    double l = 0.0;
    for (int i = 0; i < 3; ++i) l += w[i] * g_acc[i];
    for (int i = 3; i < 6; ++i) l += w[i] * 4.0 * g_acc[i];   // half-res sites
    out[0] = (float)(l / (double)NPIX);
}

// ---------------- launcher ---------------------------------------------------

template<int SI> static void run_full(cudaStream_t st, int ps) {
    row_k<SI><<<NCc * Hh / 2, 128, 0, st>>>(ps);
    col_k<SI><<<dim3(Ww / 128, Hh / Cfg<SI>::CR, NCc), 128, 0, st>>>(ps);
}
template<int SI> static void run_half(cudaStream_t st, int ps) {
    rowh_k<SI><<<dim3(HPL / 4, NCc), 128, 0, st>>>(ps);
    colh_k<SI><<<dim3(W2 / 128, H2 / 16, NCc), 128, 0, st>>>(ps);
}

extern "C" void kernel_launch(void* const* d_in, const int* in_sizes, int n_in,
                              void* d_out, int out_size) {
    (void)in_sizes; (void)n_in; (void)out_size;
    const float4* a = (const float4*)d_in[0];
    const float4* b = (const float4*)d_in[1];

    // one-time host resources (created on the uncaptured correctness call)
    static cudaStream_t sA = nullptr, sB = nullptr, sC = nullptr;
    static cudaEvent_t eD = nullptr, eA = nullptr, eB = nullptr, eC = nullptr;
    if (!sA) {
        cudaStreamCreateWithFlags(&sA, cudaStreamNonBlocking);
        cudaStreamCreateWithFlags(&sB, cudaStreamNonBlocking);
        cudaStreamCreateWithFlags(&sC, cudaStreamNonBlocking);
        cudaEventCreateWithFlags(&eD, cudaEventDisableTiming);
        cudaEventCreateWithFlags(&eA, cudaEventDisableTiming);
        cudaEventCreateWithFlags(&eB, cudaEventDisableTiming);
        cudaEventCreateWithFlags(&eC, cudaEventDisableTiming);
    }

    // legacy stream: diff, then downsample, then fork
    diff_k<<<(NPIX / 4 + 511) / 512, 512>>>(a, b);
    down_k<<<dim3(DP, NCc), 256>>>();
    cudaEventRecord(eD, 0);
    cudaStreamWaitEvent(sA, eD, 0);
    cudaStreamWaitEvent(sB, eD, 0);
    cudaStreamWaitEvent(sC, eD, 0);

    // chain A: full sigma2 + half sigma3 (plane set 0)
    run_full<2>(sA, 0);
    run_half<3>(sA, 0);
    // chain B: full sigma1 + half sigma4 (plane set 1)
    run_full<1>(sB, 1);
    run_half<4>(sB, 1);
    // chain C: full sigma0 + half sigma5 (plane set 2)
    run_full<0>(sC, 2);
    run_half<5>(sC, 2);

    cudaEventRecord(eA, sA);
    cudaEventRecord(eB, sB);
    cudaEventRecord(eC, sC);
    cudaStreamWaitEvent(0, eA, 0);
    cudaStreamWaitEvent(0, eB, 0);
    cudaStreamWaitEvent(0, eC, 0);

    final_k<<<1, 1>>>((float*)d_out);                // legacy stream
}

// round 10
// speedup vs baseline: 2.7110x; 1.0068x over previous
#include <cuda_runtime.h>

// ---------------------------------------------------------------------------
// SpatialFrequencyLoss: sum_i w_i * mean( (LoG_i * (input - target))^2 )
// LoG kernel is rank-3 separable:  a = f (x) u  +  u (x) f  -  c * ones
// sigma0-2 (K=5,11,21): FUSED per-tile kernels — stage 64x64(+halo) tile,
//   row pass into SMEM (FH,A1 tiles), col pass from SMEM, reduce. No global
//   intermediate planes at all.
// sigma3-5 (K=39,77,155): half-res cascade (R9, proven): 2x box-downsampled
//   diff with exact block-summed taps; padded D plane -> no boundary approx.
// 3 concurrent stream chains (teardown-proven topology).
// ---------------------------------------------------------------------------

namespace {
constexpr int Hh = 512, Ww = 512, NCc = 4 * 3;
constexpr int NPIX = NCc * Hh * Ww;      // 3,145,728
constexpr int W2 = 256, H2 = 256, GPAD = 40;
constexpr int DP = W2 + 2 * GPAD;        // 336 padded dim for D
constexpr int HPL = 336;                 // padded plane height
}

__device__ float  g_diff[NPIX];
__device__ float  g_Dh[NCc * DP * DP];   // padded downsampled diff
__device__ unsigned long long g_FHh[3][NCc * HPL * W2];  // half (aU,aF)
__device__ float  g_A1h[3][NCc * HPL * W2];              // half box plane
__device__ double g_acc[6];

// ---------------- f32x2 packed helpers --------------------------------------

__device__ __forceinline__ unsigned long long pk2(float lo, float hi) {
    unsigned long long r;
    asm("mov.b64 %0, {%1, %2};" : "=l"(r) : "f"(lo), "f"(hi));
    return r;
}
__device__ __forceinline__ unsigned long long ffma2(unsigned long long a,
                                                    unsigned long long b,
                                                    unsigned long long c) {
    unsigned long long d;
    asm("fma.rn.f32x2 %0, %1, %2, %3;" : "=l"(d) : "l"(a), "l"(b), "l"(c));
    return d;
}
__device__ __forceinline__ float2 upk(unsigned long long a) {
    float2 v;
    asm("mov.b64 {%0, %1}, %2;" : "=f"(v.x), "=f"(v.y) : "l"(a));
    return v;
}

// ---------------- compile-time taps ----------------------------------------

__host__ __device__ constexpr double cexp(double x) {
    double r = x; int n = 0;
    while (r < -0.5) { r += 1.0; ++n; }
    double term = 1.0, sum = 1.0;
    for (int i = 1; i < 30; ++i) { term *= r / (double)i; sum += term; }
    for (int i = 0; i < n; ++i) sum /= 2.71828182845904523536028747135266;
    return sum;
}
__host__ __device__ constexpr double u_at(int x, int P, double ss) {
    if (x < -P || x > P) return 0.0;
    return cexp(-((double)x * x) / (2.0 * ss));
}
__host__ __device__ constexpr double f_at(int x, int P, double ss, double norm) {
    if (x < -P || x > P) return 0.0;
    return ((double)x * x - ss) * cexp(-((double)x * x) / (2.0 * ss)) * norm;
}

template<int K> struct TapsT { float f[K]; float h[K]; float c; };

template<int K>
__host__ __device__ constexpr TapsT<K> make_taps(double sigma) {
    TapsT<K> T{};
    const double ss = sigma * sigma;
    const double norm = 1.0 / (2.0 * 3.14159265358979323846 * ss * ss);
    const int P = K / 2;
    double Sf = 0.0, Sh = 0.0;
    for (int i = 0; i < K; ++i) {
        const double fv = f_at(i - P, P, ss, norm);
        const double uv = u_at(i - P, P, ss);
        T.f[i] = (float)fv;
        T.h[i] = (float)uv;
        Sf += fv; Sh += uv;
    }
    T.c = (float)(2.0 * Sf * Sh / ((double)K * (double)K));
    return T;
}

template<int K2> struct TapsH { float F[K2]; float U[K2]; float c; };

template<int K2>
__host__ __device__ constexpr TapsH<K2> make_tapsH(double sigma, int K, int PL) {
    TapsH<K2> T{};
    const double ss = sigma * sigma;
    const double norm = 1.0 / (2.0 * 3.14159265358979323846 * ss * ss);
    const int P = K / 2;
    for (int t = 0; t < K2; ++t) {
        const int v = t - PL;
        T.F[t] = (float)(f_at(2 * v, P, ss, norm) + f_at(2 * v + 1, P, ss, norm));
        T.U[t] = (float)(u_at(2 * v, P, ss) + u_at(2 * v + 1, P, ss));
    }
    double Sf = 0.0, Sh = 0.0;
    for (int x = -P; x <= P; ++x) { Sf += f_at(x, P, ss, norm); Sh += u_at(x, P, ss); }
    T.c = (float)(8.0 * Sf * Sh / ((double)K * (double)K));
    return T;
}

template<int SI> struct Cfg;
template<> struct Cfg<0> { static constexpr int K = 5;  static constexpr double S = 0.6; };
template<> struct Cfg<1> { static constexpr int K = 11; static constexpr double S = 1.2; };
template<> struct Cfg<2> { static constexpr int K = 21; static constexpr double S = 2.4; };

template<int SI> struct CH;
template<> struct CH<3> { static constexpr int K = 39;  static constexpr double S = 4.8;  static constexpr int K2 = 20; static constexpr int PL = 10; static constexpr int PR = 9;  };
template<> struct CH<4> { static constexpr int K = 77;  static constexpr double S = 9.6;  static constexpr int K2 = 39; static constexpr int PL = 19; static constexpr int PR = 19; };
template<> struct CH<5> { static constexpr int K = 155; static constexpr double S = 19.2; static constexpr int K2 = 78; static constexpr int PL = 39; static constexpr int PR = 38; };

// SMEM layout for the fused full-res kernels
template<int SI> struct FSz {
    static constexpr int K   = Cfg<SI>::K;
    static constexpr int P   = K / 2;
    static constexpr int IW  = 64 + 2 * P;
    static constexpr int IWp = (IW + 3) & ~3;
    static constexpr int OFF_FH = (IW * IWp * 4 + 15) & ~15;
    static constexpr int OFF_A1 = OFF_FH + IW * 64 * 8;
    static constexpr int BYTES  = OFF_A1 + IW * 64 * 4;
};

__device__ __forceinline__ int refl(int i, int n) {
    if (i < 0) i = -i;
    if (i >= n) i = 2 * n - 2 - i;
    return i;
}

// ---------------- diff ------------------------------------------------------

__global__ void diff_k(const float4* __restrict__ a, const float4* __restrict__ b) {
    if (blockIdx.x == 0 && threadIdx.x < 6) g_acc[threadIdx.x] = 0.0;
    int i = blockIdx.x * blockDim.x + threadIdx.x;
    if (i < NPIX / 4) {
        float4 x = a[i], y = b[i];
        float4 d;
        d.x = x.x - y.x; d.y = x.y - y.y; d.z = x.z - y.z; d.w = x.w - y.w;
        reinterpret_cast<float4*>(g_diff)[i] = d;
    }
}

// ---------------- downsample (padded, true reflected block averages) --------

__global__ void down_k() {
    const int img = blockIdx.y;
    const int yy  = blockIdx.x;
    const int wy  = yy - GPAD;
    const float* __restrict__ src = g_diff + img * (Hh * Ww);
    const int r0 = refl(2 * wy, Hh), r1 = refl(2 * wy + 1, Hh);
    float* __restrict__ dst = g_Dh + (img * DP + yy) * DP;
    for (int xx = threadIdx.x; xx < DP; xx += blockDim.x) {
        const int wx = xx - GPAD;
        const int c0 = refl(2 * wx, Ww), c1 = refl(2 * wx + 1, Ww);
        dst[xx] = 0.25f * (src[r0 * Ww + c0] + src[r0 * Ww + c1] +
                           src[r1 * Ww + c0] + src[r1 * Ww + c1]);
    }
}

// ---------------- fused full-res kernel (sigma0-2) ---------------------------
// One block = one 64x64 output tile. Stage reflected input (IW x IW), row
// pass into SMEM (FH,A1), col pass from SMEM, square+reduce -> atomicAdd.

template<int SI>
__global__ void __launch_bounds__(256) fused_k() {
    constexpr int K = Cfg<SI>::K;
    constexpr TapsT<K> T = make_taps<K>(Cfg<SI>::S);
    constexpr int P   = FSz<SI>::P;
    constexpr int IW  = FSz<SI>::IW;
    constexpr int IWp = FSz<SI>::IWp;

    extern __shared__ char smem[];
    float* __restrict__ IN = reinterpret_cast<float*>(smem);
    unsigned long long* __restrict__ FHs =
        reinterpret_cast<unsigned long long*>(smem + FSz<SI>::OFF_FH);
    float* __restrict__ A1s = reinterpret_cast<float*>(smem + FSz<SI>::OFF_A1);

    const int tid = threadIdx.x;
    const int tx0 = blockIdx.x * 64, ty0 = blockIdx.y * 64;
    const int img = blockIdx.z;
    const float* __restrict__ src = g_diff + img * (Hh * Ww);

    // stage reflected input tile
    for (int idx = tid; idx < IW * IW; idx += 256) {
        const int r = idx / IW, c = idx - r * IW;
        IN[r * IWp + c] = src[refl(ty0 + r - P, Hh) * Ww + refl(tx0 + c - P, Ww)];
    }
    __syncthreads();

    // ---- row phase: 8 threads/row x 8 outputs; 32 rows per sweep ----
    {
        const int x0   = (tid & 7) * 8;
        const int rgrp = tid >> 3;
        for (int r = rgrp; r < IW; r += 32) {
            const float* __restrict__ sr = IN + r * IWp + x0;

            float w[12];
#pragma unroll
            for (int i = 0; i < 8; i += 4) {
                const float4 v = *reinterpret_cast<const float4*>(sr + i);
                w[i] = v.x; w[i + 1] = v.y; w[i + 2] = v.z; w[i + 3] = v.w;
            }
            unsigned long long aFH[8];
#pragma unroll
            for (int o = 0; o < 8; ++o) aFH[o] = 0ull;
            float S = 0.f;

            constexpr int G = K / 4, REM = K % 4;
#pragma unroll
            for (int tg = 0; tg < G; ++tg) {
                const float4 v = *reinterpret_cast<const float4*>(sr + 8 + 4 * tg);
                w[8] = v.x; w[9] = v.y; w[10] = v.z; w[11] = v.w;
#pragma unroll
                for (int j = 0; j < 4; ++j) {
                    const int t = 4 * tg + j;
                    const unsigned long long tp = pk2(T.f[t], T.h[t]);
                    S += w[j];
#pragma unroll
                    for (int o = 0; o < 8; ++o) {
                        const unsigned long long dd = pk2(w[j + o], w[j + o]);
                        aFH[o] = ffma2(tp, dd, aFH[o]);
                    }
                }
#pragma unroll
                for (int i = 0; i < 8; ++i) w[i] = w[i + 4];
            }
            if (REM >= 2) w[8] = sr[4 * G + 8];
            if (REM == 3) w[9] = sr[4 * G + 9];
#pragma unroll
            for (int j = 0; j < REM; ++j) {
                const int t = 4 * G + j;
                const unsigned long long tp = pk2(T.f[t], T.h[t]);
                S += w[j];
#pragma unroll
                for (int o = 0; o < 8; ++o) {
                    const unsigned long long dd = pk2(w[j + o], w[j + o]);
                    aFH[o] = ffma2(tp, dd, aFH[o]);
                }
            }

            float box[8];
            box[0] = S;
#pragma unroll
            for (int o = 1; o < 8; ++o)
                box[o] = box[o - 1] - sr[o - 1] + sr[o + K - 1];

            unsigned long long* __restrict__ fh = FHs + r * 64 + x0;
            float* __restrict__ a1 = A1s + r * 64 + x0;
#pragma unroll
            for (int o = 0; o < 8; ++o) {
                const float2 p = upk(aFH[o]);     // x = aF, y = aH
                fh[o] = pk2(p.y, p.x);            // store (aH, aF)
                a1[o] = box[o];
            }
        }
    }
    __syncthreads();

    // ---- col phase: 64 x-lanes x 16 y-outputs (4 groups) ----
    float local = 0.f;
    {
        const int x  = tid & 63;
        const int y0 = (tid >> 6) * 16;
        const unsigned long long* __restrict__ fcol = FHs + x;
        const float* __restrict__ acol = A1s + x;

        unsigned long long ring[16], acc[16];
#pragma unroll
        for (int o = 0; o < 16; ++o) acc[o] = 0ull;
#pragma unroll
        for (int j = 0; j < 15; ++j) ring[j] = fcol[(y0 + j) * 64];

#pragma unroll
        for (int t = 0; t < K; ++t) {
            ring[(t + 15) & 15] = fcol[(y0 + t + 15) * 64];
            const unsigned long long tp = pk2(T.f[t], T.h[t]);
#pragma unroll
            for (int o = 0; o < 16; ++o)
                acc[o] = ffma2(tp, ring[(t + o) & 15], acc[o]);
        }

        float S = 0.f;
#pragma unroll
        for (int j = 0; j < K; ++j) S += acol[(y0 + j) * 64];

        float box = S;
#pragma unroll
        for (int o = 0; o < 16; ++o) {
            if (o) box += acol[(y0 + K - 1 + o) * 64] - acol[(y0 + o - 1) * 64];
            const float2 p = upk(acc[o]);
            const float v = fmaf(-T.c, box, p.x + p.y);
            local = fmaf(v, v, local);
        }
    }

    // ---- reduce ----
#pragma unroll
    for (int off = 16; off; off >>= 1)
        local += __shfl_xor_sync(0xffffffffu, local, off);
    __shared__ float ws[8];
    if ((tid & 31) == 0) ws[tid >> 5] = local;
    __syncthreads();
    if (tid == 0) {
        double tot = 0.0;
#pragma unroll
        for (int i = 0; i < 8; ++i) tot += (double)ws[i];
        atomicAdd(&g_acc[SI], tot);
    }
}

// ---------------- half-res row pass (R9, proven) ----------------------------

template<int SI>
__global__ void __launch_bounds__(128) rowh_k(int ps) {
    constexpr int K2 = CH<SI>::K2, PL = CH<SI>::PL, PR = CH<SI>::PR;
    constexpr TapsH<K2> T = make_tapsH<K2>(CH<SI>::S, CH<SI>::K, PL);
    constexpr int PW = W2 + PL + PR;
    constexpr int PWpad = (PW + 3) & ~3;

    __shared__ alignas(16) float s[4 * PWpad];
    const int tid = threadIdx.x;
    const int img = blockIdx.y;
    const int yy0 = blockIdx.x * 4;
    const float* __restrict__ src = g_Dh + (img * DP + yy0) * DP + (GPAD - PL);

    for (int idx = tid; idx < 4 * PW; idx += 128) {
        const int rr = idx / PW, j = idx - rr * PW;
        s[rr * PWpad + j] = src[rr * DP + j];
    }
    __syncthreads();

    const int sub = tid >> 5;
    const int x0  = (tid & 31) * 8;
    const float* __restrict__ sr = s + sub * PWpad + x0;

    float w[12];
#pragma unroll
    for (int i = 0; i < 8; i += 4) {
        const float4 v = *reinterpret_cast<const float4*>(sr + i);
        w[i] = v.x; w[i + 1] = v.y; w[i + 2] = v.z; w[i + 3] = v.w;
    }

    unsigned long long aFH[8];
#pragma unroll
    for (int o = 0; o < 8; ++o) aFH[o] = 0ull;
    float S = 0.f;

    constexpr int G = K2 / 4, REM = K2 % 4;
#pragma unroll
    for (int tg = 0; tg < G; ++tg) {
        const float4 v = *reinterpret_cast<const float4*>(sr + 8 + 4 * tg);
        w[8] = v.x; w[9] = v.y; w[10] = v.z; w[11] = v.w;
#pragma unroll
        for (int j = 0; j < 4; ++j) {
            const int t = 4 * tg + j;
            const unsigned long long tp = pk2(T.F[t], T.U[t]);
            S += w[j];
#pragma unroll
            for (int o = 0; o < 8; ++o) {
                const unsigned long long dd = pk2(w[j + o], w[j + o]);
                aFH[o] = ffma2(tp, dd, aFH[o]);
            }
        }
#pragma unroll
        for (int i = 0; i < 8; ++i) w[i] = w[i + 4];
    }
    if (REM >= 2) w[8] = sr[4 * G + 8];
    if (REM == 3) w[9] = sr[4 * G + 9];
#pragma unroll
    for (int j = 0; j < REM; ++j) {
        const int t = 4 * G + j;
        const unsigned long long tp = pk2(T.F[t], T.U[t]);
        S += w[j];
#pragma unroll
        for (int o = 0; o < 8; ++o) {
            const unsigned long long dd = pk2(w[j + o], w[j + o]);
            aFH[o] = ffma2(tp, dd, aFH[o]);
        }
    }

    float box[8];
    box[0] = S;
#pragma unroll
    for (int o = 1; o < 8; ++o)
        box[o] = box[o - 1] - sr[o - 1] + sr[o + K2 - 1];

    const int base = (img * HPL + yy0 + sub) * W2 + x0;
    unsigned long long* __restrict__ fh = g_FHh[ps] + base;
#pragma unroll
    for (int o = 0; o < 8; ++o) {
        const float2 p = upk(aFH[o]);          // x = aF, y = aU
        fh[o] = pk2(p.y, p.x);                 // store (aU, aF)
    }
    float* __restrict__ a1 = g_A1h[ps] + base;
    *reinterpret_cast<float4*>(a1)     = make_float4(box[0], box[1], box[2], box[3]);
    *reinterpret_cast<float4*>(a1 + 4) = make_float4(box[4], box[5], box[6], box[7]);
}

// ---------------- half-res col pass (R9, proven) ----------------------------

template<int SI>
__global__ void __launch_bounds__(128) colh_k(int ps) {
    constexpr int K2 = CH<SI>::K2, PL = CH<SI>::PL;
    constexpr TapsH<K2> T = make_tapsH<K2>(CH<SI>::S, CH<SI>::K, PL);
    constexpr int R = 16;
    constexpr int PF = 6;
    constexpr int PI = (PF < K2) ? PF : K2;

    const int x   = blockIdx.x * 128 + threadIdx.x;
    const int y0  = blockIdx.y * R;
    const int img = blockIdx.z;
    const unsigned long long* __restrict__ FH = g_FHh[ps];
    const float* __restrict__ A1 = g_A1h[ps];
    const int pb = img * (HPL * W2) + x + (y0 - PL + GPAD) * W2;

    auto ridx = [&](int j) -> int { return pb + j * W2; };

    unsigned long long ring[R], acc[R];
#pragma unroll
    for (int o = 0; o < R; ++o) acc[o] = 0ull;

#pragma unroll
    for (int j = 0; j < R - 1; ++j) ring[j] = FH[ridx(j)];
    unsigned long long pend[PF];
#pragma unroll
    for (int q = 0; q < PI; ++q) pend[q] = FH[ridx(R - 1 + q)];

#pragma unroll
    for (int t = 0; t < K2; ++t) {
        const unsigned long long v = pend[t % PF];
        if (t + PF < K2) pend[t % PF] = FH[ridx(R - 1 + t + PF)];
        const int sl = (t + R - 1) & (R - 1);
        ring[sl] = v;
        const unsigned long long tp = pk2(T.F[t], T.U[t]);
#pragma unroll
        for (int o = 0; o < R; ++o)
            acc[o] = ffma2(tp, ring[(t + o) & (R - 1)], acc[o]);
    }

    float S = 0.f;
#pragma unroll
    for (int j = 0; j < K2; ++j) S += A1[ridx(j)];

    float box = S, local = 0.f;
#pragma unroll
    for (int o = 0; o < R; ++o) {
        if (o) box += A1[ridx(K2 - 1 + o)] - A1[ridx(o - 1)];
        const float2 p = upk(acc[o]);
        const float v = fmaf(-T.c, box, p.x + p.y);
        local = fmaf(v, v, local);
    }

#pragma unroll
    for (int off = 16; off; off >>= 1)
        local += __shfl_xor_sync(0xffffffffu, local, off);
    __shared__ float ws[4];
    if ((threadIdx.x & 31) == 0) ws[threadIdx.x >> 5] = local;
    __syncthreads();
    if (threadIdx.x == 0) {
        const double tot = (double)ws[0] + (double)ws[1] + (double)ws[2] + (double)ws[3];
        atomicAdd(&g_acc[SI], tot);
    }
}

// ---------------- final -----------------------------------------------------

__global__ void final_k(float* __restrict__ out) {
    const double w[6] = {600.0, 500.0, 400.0, 20.0, 10.0, 10.0};
    double l = 0.0;
    for (int i = 0; i < 3; ++i) l += w[i] * g_acc[i];
    for (int i = 3; i < 6; ++i) l += w[i] * 4.0 * g_acc[i];   // half-res sites
    out[0] = (float)(l / (double)NPIX);
}

// ---------------- launcher ---------------------------------------------------

template<int SI> static void run_fused(cudaStream_t st) {
    fused_k<SI><<<dim3(Ww / 64, Hh / 64, NCc), 256, FSz<SI>::BYTES, st>>>();
}
template<int SI> static void run_half(cudaStream_t st, int ps) {
    rowh_k<SI><<<dim3(HPL / 4, NCc), 128, 0, st>>>(ps);
    colh_k<SI><<<dim3(W2 / 128, H2 / 16, NCc), 128, 0, st>>>(ps);
}

extern "C" void kernel_launch(void* const* d_in, const int* in_sizes, int n_in,
                              void* d_out, int out_size) {
    (void)in_sizes; (void)n_in; (void)out_size;
    const float4* a = (const float4*)d_in[0];
    const float4* b = (const float4*)d_in[1];

    // one-time host resources (created on the uncaptured correctness call)
    static cudaStream_t sA = nullptr, sB = nullptr, sC = nullptr;
    static cudaEvent_t eD = nullptr, eA = nullptr, eB = nullptr, eC = nullptr;
    if (!sA) {
        cudaStreamCreateWithFlags(&sA, cudaStreamNonBlocking);
        cudaStreamCreateWithFlags(&sB, cudaStreamNonBlocking);
        cudaStreamCreateWithFlags(&sC, cudaStreamNonBlocking);
        cudaEventCreateWithFlags(&eD, cudaEventDisableTiming);
        cudaEventCreateWithFlags(&eA, cudaEventDisableTiming);
        cudaEventCreateWithFlags(&eB, cudaEventDisableTiming);
        cudaEventCreateWithFlags(&eC, cudaEventDisableTiming);
        cudaFuncSetAttribute(fused_k<0>, cudaFuncAttributeMaxDynamicSharedMemorySize, FSz<0>::BYTES);
        cudaFuncSetAttribute(fused_k<1>, cudaFuncAttributeMaxDynamicSharedMemorySize, FSz<1>::BYTES);
        cudaFuncSetAttribute(fused_k<2>, cudaFuncAttributeMaxDynamicSharedMemorySize, FSz<2>::BYTES);
    }

    // legacy stream: diff, then downsample, then fork
    diff_k<<<(NPIX / 4 + 511) / 512, 512>>>(a, b);
    down_k<<<dim3(DP, NCc), 256>>>();
    cudaEventRecord(eD, 0);
    cudaStreamWaitEvent(sA, eD, 0);
    cudaStreamWaitEvent(sB, eD, 0);
    cudaStreamWaitEvent(sC, eD, 0);

    // chain A: fused sigma2 + half sigma3 (plane set 0)
    run_fused<2>(sA);
    run_half<3>(sA, 0);
    // chain B: fused sigma1 + half sigma4 (plane set 1)
    run_fused<1>(sB);
    run_half<4>(sB, 1);
    // chain C: fused sigma0 + half sigma5 (plane set 2)
    run_fused<0>(sC);
    run_half<5>(sC, 2);

    cudaEventRecord(eA, sA);
    cudaEventRecord(eB, sB);
    cudaEventRecord(eC, sC);
    cudaStreamWaitEvent(0, eA, 0);
    cudaStreamWaitEvent(0, eB, 0);
    cudaStreamWaitEvent(0, eC, 0);

    final_k<<<1, 1>>>((float*)d_out);                // legacy stream
}

// round 11
// speedup vs baseline: 2.8749x; 1.0604x over previous
#include <cuda_runtime.h>

// ---------------------------------------------------------------------------
// SpatialFrequencyLoss: sum_i w_i * mean( (LoG_i * (input - target))^2 )
// LoG kernel is rank-3 separable:  a = f (x) u  +  u (x) f  -  c * ones
// sigma0-2 (K=5,11,21): fused per-tile kernels on full-res diff (R10).
// sigma3-5 (K=39,77,155): fused per-tile kernels on the 2x box-downsampled
//   padded diff plane (R9 cascade math), row+col in one kernel, no global
//   intermediate planes anywhere.
// 3 concurrent stream chains of exactly TWO kernels each.
// ---------------------------------------------------------------------------

namespace {
constexpr int Hh = 512, Ww = 512, NCc = 4 * 3;
constexpr int NPIX = NCc * Hh * Ww;      // 3,145,728
constexpr int W2 = 256, H2 = 256, GPAD = 40;
constexpr int DP = W2 + 2 * GPAD;        // 336 padded dim for D
}

__device__ float  g_diff[NPIX];
__device__ float  g_Dh[NCc * DP * DP];   // padded downsampled diff
__device__ double g_acc[6];

// ---------------- f32x2 packed helpers --------------------------------------

__device__ __forceinline__ unsigned long long pk2(float lo, float hi) {
    unsigned long long r;
    asm("mov.b64 %0, {%1, %2};" : "=l"(r) : "f"(lo), "f"(hi));
    return r;
}
__device__ __forceinline__ unsigned long long ffma2(unsigned long long a,
                                                    unsigned long long b,
                                                    unsigned long long c) {
    unsigned long long d;
    asm("fma.rn.f32x2 %0, %1, %2, %3;" : "=l"(d) : "l"(a), "l"(b), "l"(c));
    return d;
}
__device__ __forceinline__ float2 upk(unsigned long long a) {
    float2 v;
    asm("mov.b64 {%0, %1}, %2;" : "=f"(v.x), "=f"(v.y) : "l"(a));
    return v;
}

// ---------------- compile-time taps ----------------------------------------

__host__ __device__ constexpr double cexp(double x) {
    double r = x; int n = 0;
    while (r < -0.5) { r += 1.0; ++n; }
    double term = 1.0, sum = 1.0;
    for (int i = 1; i < 30; ++i) { term *= r / (double)i; sum += term; }
    for (int i = 0; i < n; ++i) sum /= 2.71828182845904523536028747135266;
    return sum;
}
__host__ __device__ constexpr double u_at(int x, int P, double ss) {
    if (x < -P || x > P) return 0.0;
    return cexp(-((double)x * x) / (2.0 * ss));
}
__host__ __device__ constexpr double f_at(int x, int P, double ss, double norm) {
    if (x < -P || x > P) return 0.0;
    return ((double)x * x - ss) * cexp(-((double)x * x) / (2.0 * ss)) * norm;
}

template<int K> struct TapsT { float f[K]; float h[K]; float c; };

template<int K>
__host__ __device__ constexpr TapsT<K> make_taps(double sigma) {
    TapsT<K> T{};
    const double ss = sigma * sigma;
    const double norm = 1.0 / (2.0 * 3.14159265358979323846 * ss * ss);
    const int P = K / 2;
    double Sf = 0.0, Sh = 0.0;
    for (int i = 0; i < K; ++i) {
        const double fv = f_at(i - P, P, ss, norm);
        const double uv = u_at(i - P, P, ss);
        T.f[i] = (float)fv;
        T.h[i] = (float)uv;
        Sf += fv; Sh += uv;
    }
    T.c = (float)(2.0 * Sf * Sh / ((double)K * (double)K));
    return T;
}

template<int K2> struct TapsH { float F[K2]; float U[K2]; float c; };

template<int K2>
__host__ __device__ constexpr TapsH<K2> make_tapsH(double sigma, int K, int PL) {
    TapsH<K2> T{};
    const double ss = sigma * sigma;
    const double norm = 1.0 / (2.0 * 3.14159265358979323846 * ss * ss);
    const int P = K / 2;
    for (int t = 0; t < K2; ++t) {
        const int v = t - PL;
        T.F[t] = (float)(f_at(2 * v, P, ss, norm) + f_at(2 * v + 1, P, ss, norm));
        T.U[t] = (float)(u_at(2 * v, P, ss) + u_at(2 * v + 1, P, ss));
    }
    double Sf = 0.0, Sh = 0.0;
    for (int x = -P; x <= P; ++x) { Sf += f_at(x, P, ss, norm); Sh += u_at(x, P, ss); }
    T.c = (float)(8.0 * Sf * Sh / ((double)K * (double)K));
    return T;
}

template<int SI> struct Cfg;
template<> struct Cfg<0> { static constexpr int K = 5;  static constexpr double S = 0.6; };
template<> struct Cfg<1> { static constexpr int K = 11; static constexpr double S = 1.2; };
template<> struct Cfg<2> { static constexpr int K = 21; static constexpr double S = 2.4; };

template<int SI> struct CH;
template<> struct CH<3> { static constexpr int K = 39;  static constexpr double S = 4.8;  static constexpr int K2 = 20; static constexpr int PL = 10; static constexpr int PR = 9;  };
template<> struct CH<4> { static constexpr int K = 77;  static constexpr double S = 9.6;  static constexpr int K2 = 39; static constexpr int PL = 19; static constexpr int PR = 19; };
template<> struct CH<5> { static constexpr int K = 155; static constexpr double S = 19.2; static constexpr int K2 = 78; static constexpr int PL = 39; static constexpr int PR = 38; };

// SMEM layouts
template<int SI> struct FSz {          // full-res fused
    static constexpr int K   = Cfg<SI>::K;
    static constexpr int P   = K / 2;
    static constexpr int IW  = 64 + 2 * P;
    static constexpr int IWp = (IW + 3) & ~3;
    static constexpr int OFF_FH = (IW * IWp * 4 + 15) & ~15;
    static constexpr int OFF_A1 = OFF_FH + IW * 64 * 8;
    static constexpr int BYTES  = OFF_A1 + IW * 64 * 4;
};
template<int SI> struct HSz {          // half-res fused
    static constexpr int K2  = CH<SI>::K2;
    static constexpr int IW  = 64 + CH<SI>::PL + CH<SI>::PR;   // = 63 + K2
    static constexpr int IWp = (IW + 3) & ~3;
    static constexpr int OFF_FH = (IW * IWp * 4 + 15) & ~15;
    static constexpr int OFF_A1 = OFF_FH + IW * 64 * 8;
    static constexpr int BYTES  = OFF_A1 + IW * 64 * 4;
};

__device__ __forceinline__ int refl(int i, int n) {
    if (i < 0) i = -i;
    if (i >= n) i = 2 * n - 2 - i;
    return i;
}

// ---------------- diff ------------------------------------------------------

__global__ void diff_k(const float4* __restrict__ a, const float4* __restrict__ b) {
    if (blockIdx.x == 0 && threadIdx.x < 6) g_acc[threadIdx.x] = 0.0;
    int i = blockIdx.x * blockDim.x + threadIdx.x;
    if (i < NPIX / 4) {
        float4 x = a[i], y = b[i];
        float4 d;
        d.x = x.x - y.x; d.y = x.y - y.y; d.z = x.z - y.z; d.w = x.w - y.w;
        reinterpret_cast<float4*>(g_diff)[i] = d;
    }
}

// ---------------- downsample (padded, true reflected block averages) --------

__global__ void down_k() {
    const int img = blockIdx.y;
    const int yy  = blockIdx.x;
    const int wy  = yy - GPAD;
    const float* __restrict__ src = g_diff + img * (Hh * Ww);
    const int r0 = refl(2 * wy, Hh), r1 = refl(2 * wy + 1, Hh);
    float* __restrict__ dst = g_Dh + (img * DP + yy) * DP;
    for (int xx = threadIdx.x; xx < DP; xx += blockDim.x) {
        const int wx = xx - GPAD;
        const int c0 = refl(2 * wx, Ww), c1 = refl(2 * wx + 1, Ww);
        dst[xx] = 0.25f * (src[r0 * Ww + c0] + src[r0 * Ww + c1] +
                           src[r1 * Ww + c0] + src[r1 * Ww + c1]);
    }
}

// ---------------- shared fused tile machinery --------------------------------
// Row phase: 8 threads/row x 8 outputs, rows strided by 32 groups.
// Col phase: 64 x-lanes x 4 groups of 16 y-outputs, u64 register ring.

template<int KT, int IW, int IWp>
__device__ __forceinline__ void tile_row_phase(
    const float* __restrict__ IN, unsigned long long* __restrict__ FHs,
    float* __restrict__ A1s, const float* __restrict__ tf,
    const float* __restrict__ th, int tid)
{
    const int x0   = (tid & 7) * 8;
    const int rgrp = tid >> 3;
    for (int r = rgrp; r < IW; r += 32) {
        const float* __restrict__ sr = IN + r * IWp + x0;

        float w[12];
#pragma unroll
        for (int i = 0; i < 8; i += 4) {
            const float4 v = *reinterpret_cast<const float4*>(sr + i);
            w[i] = v.x; w[i + 1] = v.y; w[i + 2] = v.z; w[i + 3] = v.w;
        }
        unsigned long long aFH[8];
#pragma unroll
        for (int o = 0; o < 8; ++o) aFH[o] = 0ull;
        float S = 0.f;

        constexpr int G = KT / 4, REM = KT % 4;
#pragma unroll
        for (int tg = 0; tg < G; ++tg) {
            const float4 v = *reinterpret_cast<const float4*>(sr + 8 + 4 * tg);
            w[8] = v.x; w[9] = v.y; w[10] = v.z; w[11] = v.w;
#pragma unroll
            for (int j = 0; j < 4; ++j) {
                const int t = 4 * tg + j;
                const unsigned long long tp = pk2(tf[t], th[t]);
                S += w[j];
#pragma unroll
                for (int o = 0; o < 8; ++o) {
                    const unsigned long long dd = pk2(w[j + o], w[j + o]);
                    aFH[o] = ffma2(tp, dd, aFH[o]);
                }
            }
#pragma unroll
            for (int i = 0; i < 8; ++i) w[i] = w[i + 4];
        }
        if (REM >= 2) w[8] = sr[4 * G + 8];
        if (REM == 3) w[9] = sr[4 * G + 9];
#pragma unroll
        for (int j = 0; j < REM; ++j) {
            const int t = 4 * G + j;
            const unsigned long long tp = pk2(tf[t], th[t]);
            S += w[j];
#pragma unroll
            for (int o = 0; o < 8; ++o) {
                const unsigned long long dd = pk2(w[j + o], w[j + o]);
                aFH[o] = ffma2(tp, dd, aFH[o]);
            }
        }

        float box[8];
        box[0] = S;
#pragma unroll
        for (int o = 1; o < 8; ++o)
            box[o] = box[o - 1] - sr[o - 1] + sr[o + KT - 1];

        unsigned long long* __restrict__ fh = FHs + r * 64 + x0;
        float* __restrict__ a1 = A1s + r * 64 + x0;
#pragma unroll
        for (int o = 0; o < 8; ++o) {
            const float2 p = upk(aFH[o]);     // x = aF, y = aH
            fh[o] = pk2(p.y, p.x);            // store (aH, aF)
            a1[o] = box[o];
        }
    }
}

template<int KT>
__device__ __forceinline__ float tile_col_phase(
    const unsigned long long* __restrict__ FHs, const float* __restrict__ A1s,
    const float* __restrict__ tf, const float* __restrict__ th,
    float cc, int tid)
{
    const int x  = tid & 63;
    const int y0 = (tid >> 6) * 16;
    const unsigned long long* __restrict__ fcol = FHs + x;
    const float* __restrict__ acol = A1s + x;

    unsigned long long ring[16], acc[16];
#pragma unroll
    for (int o = 0; o < 16; ++o) acc[o] = 0ull;
#pragma unroll
    for (int j = 0; j < 15; ++j) ring[j] = fcol[(y0 + j) * 64];

#pragma unroll
    for (int t = 0; t < KT; ++t) {
        ring[(t + 15) & 15] = fcol[(y0 + t + 15) * 64];
        const unsigned long long tp = pk2(tf[t], th[t]);
#pragma unroll
        for (int o = 0; o < 16; ++o)
            acc[o] = ffma2(tp, ring[(t + o) & 15], acc[o]);
    }

    float S = 0.f;
#pragma unroll
    for (int j = 0; j < KT; ++j) S += acol[(y0 + j) * 64];

    float box = S, local = 0.f;
#pragma unroll
    for (int o = 0; o < 16; ++o) {
        if (o) box += acol[(y0 + KT - 1 + o) * 64] - acol[(y0 + o - 1) * 64];
        const float2 p = upk(acc[o]);
        const float v = fmaf(-cc, box, p.x + p.y);
        local = fmaf(v, v, local);
    }
    return local;
}

__device__ __forceinline__ void tile_reduce(float local, int tid, int si) {
#pragma unroll
    for (int off = 16; off; off >>= 1)
        local += __shfl_xor_sync(0xffffffffu, local, off);
    __shared__ float ws[8];
    if ((tid & 31) == 0) ws[tid >> 5] = local;
    __syncthreads();
    if (tid == 0) {
        double tot = 0.0;
#pragma unroll
        for (int i = 0; i < 8; ++i) tot += (double)ws[i];
        atomicAdd(&g_acc[si], tot);
    }
}

// ---------------- fused full-res kernel (sigma0-2) ---------------------------

template<int SI>
__global__ void __launch_bounds__(256) fused_k() {
    constexpr int K = Cfg<SI>::K;
    constexpr TapsT<K> T = make_taps<K>(Cfg<SI>::S);
    constexpr int P   = FSz<SI>::P;
    constexpr int IW  = FSz<SI>::IW;
    constexpr int IWp = FSz<SI>::IWp;

    extern __shared__ char smem[];
    float* __restrict__ IN = reinterpret_cast<float*>(smem);
    unsigned long long* __restrict__ FHs =
        reinterpret_cast<unsigned long long*>(smem + FSz<SI>::OFF_FH);
    float* __restrict__ A1s = reinterpret_cast<float*>(smem + FSz<SI>::OFF_A1);

    const int tid = threadIdx.x;
    const int tx0 = blockIdx.x * 64, ty0 = blockIdx.y * 64;
    const int img = blockIdx.z;
    const float* __restrict__ src = g_diff + img * (Hh * Ww);

    for (int idx = tid; idx < IW * IW; idx += 256) {
        const int r = idx / IW, c = idx - r * IW;
        IN[r * IWp + c] = src[refl(ty0 + r - P, Hh) * Ww + refl(tx0 + c - P, Ww)];
    }
    __syncthreads();

    tile_row_phase<K, IW, IWp>(IN, FHs, A1s, T.f, T.h, tid);
    __syncthreads();

    const float local = tile_col_phase<K>(FHs, A1s, T.f, T.h, T.c, tid);
    tile_reduce(local, tid, SI);
}

// ---------------- fused half-res kernel (sigma3-5) ---------------------------
// Reads the padded D plane: no reflection anywhere.

template<int SI>
__global__ void __launch_bounds__(256) fusedh_k() {
    constexpr int K2 = CH<SI>::K2, PL = CH<SI>::PL;
    constexpr TapsH<K2> T = make_tapsH<K2>(CH<SI>::S, CH<SI>::K, PL);
    constexpr int IW  = HSz<SI>::IW;
    constexpr int IWp = HSz<SI>::IWp;

    extern __shared__ char smem[];
    float* __restrict__ IN = reinterpret_cast<float*>(smem);
    unsigned long long* __restrict__ FHs =
        reinterpret_cast<unsigned long long*>(smem + HSz<SI>::OFF_FH);
    float* __restrict__ A1s = reinterpret_cast<float*>(smem + HSz<SI>::OFF_A1);

    const int tid = threadIdx.x;
    const int tx0 = blockIdx.x * 64, ty0 = blockIdx.y * 64;
    const int img = blockIdx.z;
    const float* __restrict__ src =
        g_Dh + (img * DP + (ty0 - PL + GPAD)) * DP + (tx0 - PL + GPAD);

    for (int idx = tid; idx < IW * IW; idx += 256) {
        const int r = idx / IW, c = idx - r * IW;
        IN[r * IWp + c] = src[r * DP + c];
    }
    __syncthreads();

    tile_row_phase<K2, IW, IWp>(IN, FHs, A1s, T.F, T.U, tid);
    __syncthreads();

    const float local = tile_col_phase<K2>(FHs, A1s, T.F, T.U, T.c, tid);
    tile_reduce(local, tid, SI);
}

// ---------------- final -----------------------------------------------------

__global__ void final_k(float* __restrict__ out) {
    const double w[6] = {600.0, 500.0, 400.0, 20.0, 10.0, 10.0};
    double l = 0.0;
    for (int i = 0; i < 3; ++i) l += w[i] * g_acc[i];
    for (int i = 3; i < 6; ++i) l += w[i] * 4.0 * g_acc[i];   // half-res sites
    out[0] = (float)(l / (double)NPIX);
}

// ---------------- launcher ---------------------------------------------------

template<int SI> static void run_fused(cudaStream_t st) {
    fused_k<SI><<<dim3(Ww / 64, Hh / 64, NCc), 256, FSz<SI>::BYTES, st>>>();
}
template<int SI> static void run_fusedh(cudaStream_t st) {
    fusedh_k<SI><<<dim3(W2 / 64, H2 / 64, NCc), 256, HSz<SI>::BYTES, st>>>();
}

extern "C" void kernel_launch(void* const* d_in, const int* in_sizes, int n_in,
                              void* d_out, int out_size) {
    (void)in_sizes; (void)n_in; (void)out_size;
    const float4* a = (const float4*)d_in[0];
    const float4* b = (const float4*)d_in[1];

    // one-time host resources (created on the uncaptured correctness call)
    static cudaStream_t sA = nullptr, sB = nullptr, sC = nullptr;
    static cudaEvent_t eD = nullptr, eA = nullptr, eB = nullptr, eC = nullptr;
    if (!sA) {
        cudaStreamCreateWithFlags(&sA, cudaStreamNonBlocking);
        cudaStreamCreateWithFlags(&sB, cudaStreamNonBlocking);
        cudaStreamCreateWithFlags(&sC, cudaStreamNonBlocking);
        cudaEventCreateWithFlags(&eD, cudaEventDisableTiming);
        cudaEventCreateWithFlags(&eA, cudaEventDisableTiming);
        cudaEventCreateWithFlags(&eB, cudaEventDisableTiming);
        cudaEventCreateWithFlags(&eC, cudaEventDisableTiming);
        cudaFuncSetAttribute(fused_k<0>,  cudaFuncAttributeMaxDynamicSharedMemorySize, FSz<0>::BYTES);
        cudaFuncSetAttribute(fused_k<1>,  cudaFuncAttributeMaxDynamicSharedMemorySize, FSz<1>::BYTES);
        cudaFuncSetAttribute(fused_k<2>,  cudaFuncAttributeMaxDynamicSharedMemorySize, FSz<2>::BYTES);
        cudaFuncSetAttribute(fusedh_k<3>, cudaFuncAttributeMaxDynamicSharedMemorySize, HSz<3>::BYTES);
        cudaFuncSetAttribute(fusedh_k<4>, cudaFuncAttributeMaxDynamicSharedMemorySize, HSz<4>::BYTES);
        cudaFuncSetAttribute(fusedh_k<5>, cudaFuncAttributeMaxDynamicSharedMemorySize, HSz<5>::BYTES);
    }

    // legacy stream: diff, then downsample, then fork
    diff_k<<<(NPIX / 4 + 511) / 512, 512>>>(a, b);
    down_k<<<dim3(DP, NCc), 256>>>();
    cudaEventRecord(eD, 0);
    cudaStreamWaitEvent(sA, eD, 0);
    cudaStreamWaitEvent(sB, eD, 0);
    cudaStreamWaitEvent(sC, eD, 0);

    // chain A: fused sigma2 + fused-half sigma3
    run_fused<2>(sA);
    run_fusedh<3>(sA);
    // chain B: fused sigma1 + fused-half sigma4
    run_fused<1>(sB);
    run_fusedh<4>(sB);
    // chain C: fused sigma0 + fused-half sigma5
    run_fused<0>(sC);
    run_fusedh<5>(sC);

    cudaEventRecord(eA, sA);
    cudaEventRecord(eB, sB);
    cudaEventRecord(eC, sC);
    cudaStreamWaitEvent(0, eA, 0);
    cudaStreamWaitEvent(0, eB, 0);
    cudaStreamWaitEvent(0, eC, 0);

    final_k<<<1, 1>>>((float*)d_out);                // legacy stream
}